// round 8
// baseline (speedup 1.0000x reference)
#include <cuda_runtime.h>
#include <cuda_fp16.h>

#define BB    8
#define PP    16384
#define KN    16
#define CK    144
#define IMG   (16*128*128)    // 262144 = 2^18
#define NT    256
#define NPX   4               // pixels per tile
#define NTILES (PP/NPX)       // 4096
#define GRID  304             // 2 blocks/SM on 152 SMs
#define PADP  148             // patch row stride (floats)
#define WSTRIDE 2312          // per-px weight tile stride (2304+8); %32==8

#define WF    (NPX*WSTRIDE)               // 9248 floats per weight buffer
#define PF    (NPX*BB*PADP)               // 4736 floats patch
#define OF    544                         // outsm floats
#define SMEM_FLOATS (2*WF + PF + OF)      // 23776
#define SMEM_BYTES  (SMEM_FLOATS*4 + 16)  // + 2 mbarriers

// 4 MB scratch: x transposed + fp16-packed, batch-innermost (row = 16B)
__device__ __align__(16) __half g_xth[IMG * BB];
__device__ int g_idx_is64;

__device__ __forceinline__ void fma2(unsigned long long& d,
                                     unsigned long long a, unsigned long long b) {
    asm("fma.rn.f32x2 %0, %1, %2, %0;" : "+l"(d) : "l"(a), "l"(b));
}

__device__ __forceinline__ void mbar_wait(unsigned mbar, int ph) {
    asm volatile(
        "{\n\t"
        ".reg .pred P1;\n\t"
        "WL_%=:\n\t"
        "mbarrier.try_wait.parity.acquire.cta.shared::cta.b64 P1, [%0], %1, 0x989680;\n\t"
        "@P1 bra.uni WD_%=;\n\t"
        "bra.uni WL_%=;\n\t"
        "WD_%=:\n\t"
        "}\n"
        :: "r"(mbar), "r"(ph) : "memory");
}

// t==0 only: expect_tx + 4 bulk copies (9216 B each) for one tile
__device__ __forceinline__ void wcopy(int p0, const float* __restrict__ weights,
                                      float* wdst, unsigned mbar) {
    asm volatile("mbarrier.arrive.expect_tx.shared.b64 _, [%0], %1;"
                 :: "r"(mbar), "r"(NPX * KN * CK * 4) : "memory");
    #pragma unroll
    for (int px = 0; px < NPX; px++) {
        unsigned d = (unsigned)__cvta_generic_to_shared(wdst + px * WSTRIDE);
        const float* src = weights + (size_t)(p0 + px) * (KN * CK);
        asm volatile(
            "{\n\t"
            ".reg .b64 pol;\n\t"
            "createpolicy.fractional.L2::evict_first.b64 pol, 1.0;\n\t"
            "cp.async.bulk.shared::cluster.global.mbarrier::complete_tx::bytes.L2::cache_hint"
            " [%0], [%1], %2, [%3], pol;\n\t"
            "}\n"
            :: "r"(d), "l"(src), "r"(KN * CK * 4), "r"(mbar) : "memory");
    }
}

__device__ __forceinline__ void gather_load(int p0, int t, int is64,
                                            const unsigned* __restrict__ hidx32,
                                            uint4* v) {
    #pragma unroll
    for (int r = 0; r < 3; r++) {
        int e = t + r * NT;
        if (r < 2 || t < (NPX * CK - 2 * NT)) {
            int px = e / CK;
            int c  = e - px * CK;
            int elem = (p0 + px) * CK + c;
            unsigned w = is64 ? __ldcs(&hidx32[2 * elem]) : __ldcs(&hidx32[elem]);
            int row = (int)(w & (IMG - 1));
            v[r] = __ldg((const uint4*)&g_xth[(size_t)row * BB]);
        }
    }
}

__device__ __forceinline__ void gather_store(int t, const uint4* v, float* patch) {
    #pragma unroll
    for (int r = 0; r < 3; r++) {
        int e = t + r * NT;
        if (r < 2 || t < (NPX * CK - 2 * NT)) {
            int px = e / CK;
            int c  = e - px * CK;
            const __half2* hp = (const __half2*)&v[r];
            float* pr = &patch[(px * BB) * PADP + c];
            #pragma unroll
            for (int q = 0; q < 4; q++) {
                float2 f = __half22float2(hp[q]);
                pr[(2 * q) * PADP]     = f.x;
                pr[(2 * q + 1) * PADP] = f.y;
            }
        }
    }
}

// Transpose+pack x [B][IMG] -> g_xth [IMG][B]; block 0 probes idx dtype.
__global__ __launch_bounds__(NT) void transpose_kernel(
    const float* __restrict__ x, const unsigned* __restrict__ h32)
{
    if (blockIdx.x == 0 && threadIdx.x < 32) {
        unsigned v = h32[2u * (threadIdx.x * 36000u) + 1u];
        int all0 = __all_sync(0xFFFFFFFFu, v == 0u);
        if (threadIdx.x == 0) g_idx_is64 = all0;
    }
    int i = blockIdx.x * NT + threadIdx.x;
    __half2 h[4];
    #pragma unroll
    for (int q = 0; q < 4; q++) {
        float lo = __ldg(&x[(2 * q) * IMG + i]);
        float hi = __ldg(&x[(2 * q + 1) * IMG + i]);
        h[q] = __floats2half2_rn(lo, hi);
    }
    *(uint4*)&g_xth[(size_t)i * BB] = *(uint4*)h;
}

__global__ __launch_bounds__(NT, 2) void abc2d_kernel(
    const float* __restrict__ weights,
    const unsigned* __restrict__ hidx32,
    float* __restrict__ out)
{
    extern __shared__ __align__(16) float smem[];
    float* wsm[2];
    wsm[0]       = smem;                    // [NPX][WSTRIDE]
    wsm[1]       = smem + WF;
    float* patch = smem + 2 * WF;           // [NPX*BB][PADP]
    float* outsm = smem + 2 * WF + PF;      // 544
    unsigned mbarb = (unsigned)__cvta_generic_to_shared(smem + SMEM_FLOATS);

    const int t  = threadIdx.x;
    const int is64 = g_idx_is64;
    const int G = GRID;

    // compute-role constants
    const int wid  = t >> 5;
    const int lane = t & 31;
    const int s    = lane >> 4;
    const int px_c = (wid & 1) * 2 + ((lane >> 3) & 1);
    const int b    = lane & 7;
    const int k0   = (wid >> 1) * 4;        // 4 k-rows per thread

    if (t == 0) {
        asm volatile("mbarrier.init.shared.b64 [%0], 1;" :: "r"(mbarb) : "memory");
        asm volatile("mbarrier.init.shared.b64 [%0], 1;" :: "r"(mbarb + 8) : "memory");
    }
    __syncthreads();

    // ---- prologue ----
    int tile = blockIdx.x;
    uint4 gv[3];
    if (t == 0) wcopy(tile * NPX, weights, wsm[0], mbarb);
    gather_load(tile * NPX, t, is64, hidx32, gv);
    gather_store(t, gv, patch);             // stalls on the LDGs; fine once
    if (t == 0 && tile + G < NTILES) wcopy((tile + G) * NPX, weights, wsm[1], mbarb + 8);
    __syncthreads();
    if (tile + G < NTILES) gather_load((tile + G) * NPX, t, is64, hidx32, gv);

    int ph[2] = {0, 0};
    int buf = 0;

    for (; tile < NTILES; tile += G, buf ^= 1) {
        unsigned mb = mbarb + buf * 8;
        mbar_wait(mb, ph[buf]);
        ph[buf] ^= 1;

        // ---- compute (all 256 threads; 4 k-rows each, s-split over c4) ----
        unsigned long long acc[4] = {0ull, 0ull, 0ull, 0ull};
        {
            const float* wr = wsm[buf] + px_c * WSTRIDE + k0 * CK;
            const float* pr = patch + (px_c * BB + b) * PADP;
            #pragma unroll
            for (int jj = 0; jj < 18; jj++) {
                const int a4 = (jj * 2 + s) * 4;
                ulonglong2 p2 = *(const ulonglong2*)&pr[a4];
                #pragma unroll
                for (int k = 0; k < 4; k++) {
                    ulonglong2 w2 = *(const ulonglong2*)&wr[k * CK + a4];
                    fma2(acc[k], p2.x, w2.x);
                    fma2(acc[k], p2.y, w2.y);
                }
            }
        }
        float res[4];
        #pragma unroll
        for (int k = 0; k < 4; k++) {
            float lo = __uint_as_float((unsigned)acc[k]);
            float hi = __uint_as_float((unsigned)(acc[k] >> 32));
            res[k] = lo + hi;
            res[k] += __shfl_xor_sync(0xFFFFFFFFu, res[k], 16);
        }

        __syncthreads();                    // patch + wsm[buf] reads done

        int tile2 = tile + 2 * G;
        if (t == 0 && tile2 < NTILES) wcopy(tile2 * NPX, weights, wsm[buf], mb);
        if (tile + G < NTILES) gather_store(t, gv, patch);   // tile+G patch
        if (s == 0) {                       // 128 threads stage output
            int base = b * 68 + k0 * 4 + px_c;
            #pragma unroll
            for (int k = 0; k < 4; k++) outsm[base + k * 4] = res[k];
        }
        if (tile2 < NTILES) gather_load(tile2 * NPX, t, is64, hidx32, gv);
        __syncthreads();                    // outsm + patch STS visible

        if (t < KN * BB) {
            int bb = t >> 4, kk = t & 15;
            float4 v = *(const float4*)&outsm[bb * 68 + kk * 4];
            __stcs((float4*)&out[((size_t)t << 14) + tile * NPX], v);
        }
    }
}

extern "C" void kernel_launch(void* const* d_in, const int* in_sizes, int n_in,
                              void* d_out, int out_size) {
    const float*    x   = (const float*)d_in[0];
    const float*    w   = (const float*)d_in[1];
    const unsigned* hid = (const unsigned*)d_in[2];
    float*          out = (float*)d_out;
    (void)in_sizes; (void)n_in; (void)out_size;

    cudaFuncSetAttribute(abc2d_kernel,
                         cudaFuncAttributeMaxDynamicSharedMemorySize, SMEM_BYTES);
    transpose_kernel<<<IMG / NT, NT>>>(x, hid);
    abc2d_kernel<<<GRID, NT, SMEM_BYTES>>>(w, hid, out);
}

// round 9
// speedup vs baseline: 1.3108x; 1.3108x over previous
#include <cuda_runtime.h>
#include <cuda_fp16.h>

#define BB    8
#define PP    16384
#define KN    16
#define CK    144
#define IMG   (16*128*128)    // 262144 = 2^18
#define NT    128
#define NPX   2               // pixels per block
#define WSTRIDE 2312          // per-px weight tile stride (floats); 578 16B-units, %8==2
#define PADPH 148             // patch row stride in halves (296B = 37 8B-units, %16 coprime)
#define OSS   18              // outsm K-stride

#define WFL   (NPX*WSTRIDE)               // 4624 floats
#define PFL   (NPX*BB*PADPH/2)            // 1184 floats (half storage)
#define SMEM_FLOATS (WFL + PFL)           // 5808
#define SMEM_BYTES  (SMEM_FLOATS*4 + 8)   // + mbarrier

// 4 MB scratch: x transposed + fp16-packed, batch-innermost (row = 16B)
__device__ __align__(16) __half g_xth[IMG * BB];
__device__ int g_idx_is64;

__device__ __forceinline__ void fma2(unsigned long long& d,
                                     unsigned long long a, unsigned long long b) {
    asm("fma.rn.f32x2 %0, %1, %2, %0;" : "+l"(d) : "l"(a), "l"(b));
}

// Transpose+pack x [B][IMG] -> g_xth [IMG][B]; block 0 probes idx dtype.
__global__ __launch_bounds__(256) void transpose_kernel(
    const float* __restrict__ x, const unsigned* __restrict__ h32)
{
    if (blockIdx.x == 0 && threadIdx.x < 32) {
        unsigned v = h32[2u * (threadIdx.x * 36000u) + 1u];
        int all0 = __all_sync(0xFFFFFFFFu, v == 0u);
        if (threadIdx.x == 0) g_idx_is64 = all0;
    }
    int i = blockIdx.x * 256 + threadIdx.x;
    __half2 h[4];
    #pragma unroll
    for (int q = 0; q < 4; q++) {
        float lo = __ldg(&x[(2 * q) * IMG + i]);
        float hi = __ldg(&x[(2 * q + 1) * IMG + i]);
        h[q] = __floats2half2_rn(lo, hi);
    }
    *(uint4*)&g_xth[(size_t)i * BB] = *(uint4*)h;
}

__global__ __launch_bounds__(NT, 9) void abc2d_kernel(
    const float* __restrict__ weights,
    const unsigned* __restrict__ hidx32,
    float* __restrict__ out)
{
    extern __shared__ __align__(16) float smem[];
    float*  wsm   = smem;                           // [NPX][WSTRIDE]
    __half* patch = (__half*)(smem + WFL);          // [NPX][BB][PADPH]
    unsigned mbar = (unsigned)__cvta_generic_to_shared(smem + SMEM_FLOATS);

    const int p0 = blockIdx.x * NPX;
    const int t  = threadIdx.x;
    const int is64 = g_idx_is64;

    if (t == 0)
        asm volatile("mbarrier.init.shared.b64 [%0], 1;" :: "r"(mbar) : "memory");
    __syncthreads();

    // ---- weights: 2 bulk copies (9216 B each), evict-first ----
    if (t == 0) {
        asm volatile("mbarrier.arrive.expect_tx.shared.b64 _, [%0], %1;"
                     :: "r"(mbar), "r"(NPX * KN * CK * 4) : "memory");
        #pragma unroll
        for (int px = 0; px < NPX; px++) {
            unsigned d = (unsigned)__cvta_generic_to_shared(wsm + px * WSTRIDE);
            const float* src = weights + (size_t)(p0 + px) * (KN * CK);
            asm volatile(
                "{\n\t"
                ".reg .b64 pol;\n\t"
                "createpolicy.fractional.L2::evict_first.b64 pol, 1.0;\n\t"
                "cp.async.bulk.shared::cluster.global.mbarrier::complete_tx::bytes.L2::cache_hint"
                " [%0], [%1], %2, [%3], pol;\n\t"
                "}\n"
                :: "r"(d), "l"(src), "r"(KN * CK * 4), "r"(mbar) : "memory");
        }
    }

    // ---- gather (overlaps copy): 144 pair-tasks, 2 LDG.128 each ----
    {
        #pragma unroll
        for (int r = 0; r < 2; r++) {
            int pe = t + r * NT;
            if (r == 0 || t < (NPX * CK / 2 - NT)) {    // 128 + 16
                int px = pe / (CK / 2);
                int c0 = (pe - px * (CK / 2)) * 2;
                int elem = (p0 + px) * CK + c0;
                unsigned i0, i1;
                if (is64) { i0 = __ldcs(&hidx32[2 * elem]); i1 = __ldcs(&hidx32[2 * elem + 2]); }
                else      { i0 = __ldcs(&hidx32[elem]);     i1 = __ldcs(&hidx32[elem + 1]); }
                uint4 v0 = __ldg((const uint4*)&g_xth[(size_t)(i0 & (IMG - 1)) * BB]);
                uint4 v1 = __ldg((const uint4*)&g_xth[(size_t)(i1 & (IMG - 1)) * BB]);
                const unsigned* a = (const unsigned*)&v0;
                const unsigned* bq = (const unsigned*)&v1;
                #pragma unroll
                for (int q = 0; q < 4; q++) {
                    unsigned lo = __byte_perm(a[q], bq[q], 0x5410);  // b=2q:   (c0,c0+1)
                    unsigned hi = __byte_perm(a[q], bq[q], 0x7632);  // b=2q+1: (c0,c0+1)
                    *(unsigned*)&patch[(px * BB + 2 * q) * PADPH + c0]     = lo;
                    *(unsigned*)&patch[(px * BB + 2 * q + 1) * PADPH + c0] = hi;
                }
            }
        }
    }

    __syncthreads();          // patch visible

    // wait for weight copies
    asm volatile(
        "{\n\t"
        ".reg .pred P1;\n\t"
        "WL_%=:\n\t"
        "mbarrier.try_wait.parity.acquire.cta.shared::cta.b64 P1, [%0], 0, 0x989680;\n\t"
        "@P1 bra.uni WD_%=;\n\t"
        "bra.uni WL_%=;\n\t"
        "WD_%=:\n\t"
        "}\n"
        :: "r"(mbar) : "memory");

    // ---- compute: thread = (px, b, kq); k rows kq and kq+8 ----
    const int b  = t & 7;
    const int kq = ((t >> 5) << 1) | ((t >> 3) & 1);
    const int px = (t >> 4) & 1;
    float res0, res1;
    {
        const float*  wr0 = wsm + px * WSTRIDE + kq * CK;
        const float*  wr1 = wr0 + 8 * CK;
        const __half* pr  = patch + (px * BB + b) * PADPH;
        unsigned long long a0 = 0ull, a1 = 0ull;
        #pragma unroll
        for (int jj = 0; jj < 36; jj++) {
            float2 raw = *(const float2*)(pr + jj * 4);      // LDS.64: 4 halves
            float2 f01 = __half22float2(*(__half2*)&raw.x);
            float2 f23 = __half22float2(*(__half2*)&raw.y);
            ulonglong2 w0 = *(const ulonglong2*)(wr0 + jj * 4);
            ulonglong2 w1 = *(const ulonglong2*)(wr1 + jj * 4);
            fma2(a0, w0.x, *(unsigned long long*)&f01);
            fma2(a0, w0.y, *(unsigned long long*)&f23);
            fma2(a1, w1.x, *(unsigned long long*)&f01);
            fma2(a1, w1.y, *(unsigned long long*)&f23);
        }
        res0 = __uint_as_float((unsigned)a0) + __uint_as_float((unsigned)(a0 >> 32));
        res1 = __uint_as_float((unsigned)a1) + __uint_as_float((unsigned)(a1 >> 32));
    }

    // ---- staged output: outsm[K][b][px] (stride OSS), then STG.64 ----
    __syncthreads();                        // patch reads done; reuse as outsm
    float* outsm = (float*)patch;           // 16*OSS = 288 floats
    outsm[kq * OSS + b * 2 + px]       = res0;
    outsm[(kq + 8) * OSS + b * 2 + px] = res1;
    __syncthreads();

    {
        int kk = t & 15, bb = t >> 4;       // t in [0,128): row (bb,kk)
        float2 v = *(const float2*)&outsm[kk * OSS + bb * 2];
        __stcs((float2*)&out[(((size_t)bb * KN + kk) << 14) + p0], v);
    }
}

extern "C" void kernel_launch(void* const* d_in, const int* in_sizes, int n_in,
                              void* d_out, int out_size) {
    const float*    x   = (const float*)d_in[0];
    const float*    w   = (const float*)d_in[1];
    const unsigned* hid = (const unsigned*)d_in[2];
    float*          out = (float*)d_out;
    (void)in_sizes; (void)n_in; (void)out_size;

    cudaFuncSetAttribute(abc2d_kernel,
                         cudaFuncAttributeMaxDynamicSharedMemorySize, SMEM_BYTES);
    transpose_kernel<<<IMG / 256, 256>>>(x, hid);
    abc2d_kernel<<<PP / NPX, NT, SMEM_BYTES>>>(w, hid, out);
}

// round 10
// speedup vs baseline: 1.3958x; 1.0648x over previous
#include <cuda_runtime.h>
#include <cuda_fp16.h>

#define BB    8
#define PP    16384
#define KN    16
#define CK    144
#define IMG   (16*128*128)    // 262144 = 2^18
#define NT    128
#define NPX   2               // pixels per block
#define WSTRIDE 2312          // per-px weight tile stride (floats); %32==8
#define PADPH 152             // patch row stride in halves (304B, 16B-aligned, deg-2 banks)
#define OSS   18              // outsm K-stride

#define WFL   (NPX*WSTRIDE)               // 4624 floats
#define PFL   (NPX*BB*PADPH/2)            // 1216 floats (fp16 storage)
#define SMEM_FLOATS (WFL + PFL)           // 5840
#define SMEM_BYTES  (SMEM_FLOATS*4 + 8)   // + mbarrier

// 4 MB scratch: x transposed + fp16-packed, batch-innermost (row = 16B)
__device__ __align__(16) __half g_xth[IMG * BB];
__device__ int g_idx_is64;

__device__ __forceinline__ void fma2(unsigned long long& d,
                                     unsigned long long a, unsigned long long b) {
    asm("fma.rn.f32x2 %0, %1, %2, %0;" : "+l"(d) : "l"(a), "l"(b));
}

// Transpose+pack x [B][IMG] -> g_xth [IMG][B]; block 0 probes idx dtype.
__global__ __launch_bounds__(256) void transpose_kernel(
    const float* __restrict__ x, const unsigned* __restrict__ h32)
{
    if (blockIdx.x == 0 && threadIdx.x < 32) {
        unsigned v = h32[2u * (threadIdx.x * 36000u) + 1u];
        int all0 = __all_sync(0xFFFFFFFFu, v == 0u);
        if (threadIdx.x == 0) g_idx_is64 = all0;
    }
    int i = blockIdx.x * 256 + threadIdx.x;
    __half2 h[4];
    #pragma unroll
    for (int q = 0; q < 4; q++) {
        float lo = __ldg(&x[(2 * q) * IMG + i]);
        float hi = __ldg(&x[(2 * q + 1) * IMG + i]);
        h[q] = __floats2half2_rn(lo, hi);
    }
    *(uint4*)&g_xth[(size_t)i * BB] = *(uint4*)h;
}

__global__ __launch_bounds__(NT, 9) void abc2d_kernel(
    const float* __restrict__ weights,
    const unsigned* __restrict__ hidx32,
    float* __restrict__ out)
{
    extern __shared__ __align__(16) float smem[];
    float*  wsm   = smem;                           // [NPX][WSTRIDE]
    __half* patch = (__half*)(smem + WFL);          // [NPX*BB][PADPH]
    unsigned mbar = (unsigned)__cvta_generic_to_shared(smem + SMEM_FLOATS);

    const int p0 = blockIdx.x * NPX;
    const int t  = threadIdx.x;
    const int is64 = g_idx_is64;

    if (t == 0)
        asm volatile("mbarrier.init.shared.b64 [%0], 1;" :: "r"(mbar) : "memory");
    __syncthreads();

    // ---- weights: 2 bulk copies (9216 B each), evict-first ----
    if (t == 0) {
        asm volatile("mbarrier.arrive.expect_tx.shared.b64 _, [%0], %1;"
                     :: "r"(mbar), "r"(NPX * KN * CK * 4) : "memory");
        #pragma unroll
        for (int px = 0; px < NPX; px++) {
            unsigned d = (unsigned)__cvta_generic_to_shared(wsm + px * WSTRIDE);
            const float* src = weights + (size_t)(p0 + px) * (KN * CK);
            asm volatile(
                "{\n\t"
                ".reg .b64 pol;\n\t"
                "createpolicy.fractional.L2::evict_first.b64 pol, 1.0;\n\t"
                "cp.async.bulk.shared::cluster.global.mbarrier::complete_tx::bytes.L2::cache_hint"
                " [%0], [%1], %2, [%3], pol;\n\t"
                "}\n"
                :: "r"(d), "l"(src), "r"(KN * CK * 4), "r"(mbar) : "memory");
        }
    }

    // ---- gather (overlaps copy): 144 pair-tasks, 2 LDG.128 each ----
    {
        #pragma unroll
        for (int r = 0; r < 2; r++) {
            int pe = t + r * NT;
            if (r == 0 || t < (NPX * CK / 2 - NT)) {    // 128 + 16
                int px = pe / (CK / 2);
                int c0 = (pe - px * (CK / 2)) * 2;
                int elem = (p0 + px) * CK + c0;
                unsigned i0, i1;
                if (is64) { i0 = __ldcs(&hidx32[2 * elem]); i1 = __ldcs(&hidx32[2 * elem + 2]); }
                else      { i0 = __ldcs(&hidx32[elem]);     i1 = __ldcs(&hidx32[elem + 1]); }
                uint4 v0 = __ldg((const uint4*)&g_xth[(size_t)(i0 & (IMG - 1)) * BB]);
                uint4 v1 = __ldg((const uint4*)&g_xth[(size_t)(i1 & (IMG - 1)) * BB]);
                const unsigned* a = (const unsigned*)&v0;
                const unsigned* bq = (const unsigned*)&v1;
                #pragma unroll
                for (int q = 0; q < 4; q++) {
                    unsigned lo = __byte_perm(a[q], bq[q], 0x5410);  // b=2q:   (c0,c0+1)
                    unsigned hi = __byte_perm(a[q], bq[q], 0x7632);  // b=2q+1: (c0,c0+1)
                    *(unsigned*)&patch[(px * BB + 2 * q) * PADPH + c0]     = lo;
                    *(unsigned*)&patch[(px * BB + 2 * q + 1) * PADPH + c0] = hi;
                }
            }
        }
    }

    __syncthreads();          // patch visible

    // wait for weight copies
    asm volatile(
        "{\n\t"
        ".reg .pred P1;\n\t"
        "WL_%=:\n\t"
        "mbarrier.try_wait.parity.acquire.cta.shared::cta.b64 P1, [%0], 0, 0x989680;\n\t"
        "@P1 bra.uni WD_%=;\n\t"
        "bra.uni WL_%=;\n\t"
        "WD_%=:\n\t"
        "}\n"
        :: "r"(mbar) : "memory");

    // ---- compute: thread = (b, px, kq, s); 4 k-rows (kq+4j), 9 8c-chunks ----
    const int b  = t & 7;
    const int px = (t >> 3) & 1;
    const int kq = (t >> 4) & 3;
    const int s  = t >> 6;
    float res[4];
    {
        const float*  wbase = wsm + px * WSTRIDE + kq * CK;
        const __half* pr    = patch + (px * BB + b) * PADPH;
        unsigned long long acc[4] = {0ull, 0ull, 0ull, 0ull};
        #pragma unroll
        for (int ch = 0; ch < 9; ch++) {
            const int c0 = (s * 9 + ch) * 8;
            uint4 praw = *(const uint4*)(pr + c0);       // LDS.128: 8 halves
            const __half2* ph2 = (const __half2*)&praw;
            float2 f0 = __half22float2(ph2[0]);
            float2 f1 = __half22float2(ph2[1]);
            float2 f2 = __half22float2(ph2[2]);
            float2 f3 = __half22float2(ph2[3]);
            unsigned long long pf0 = *(unsigned long long*)&f0;
            unsigned long long pf1 = *(unsigned long long*)&f1;
            unsigned long long pf2 = *(unsigned long long*)&f2;
            unsigned long long pf3 = *(unsigned long long*)&f3;
            #pragma unroll
            for (int j = 0; j < 4; j++) {
                const float* wr = wbase + j * (4 * CK) + c0;
                ulonglong2 wlo = *(const ulonglong2*)wr;        // c0..c0+3
                ulonglong2 whi = *(const ulonglong2*)(wr + 4);  // c0+4..c0+7
                fma2(acc[j], wlo.x, pf0);
                fma2(acc[j], wlo.y, pf1);
                fma2(acc[j], whi.x, pf2);
                fma2(acc[j], whi.y, pf3);
            }
        }
        #pragma unroll
        for (int j = 0; j < 4; j++)
            res[j] = __uint_as_float((unsigned)acc[j]) +
                     __uint_as_float((unsigned)(acc[j] >> 32));
    }

    // ---- staged output: part[s][k][b*2+px], then merge + STG.64 ----
    __syncthreads();                        // patch reads done; reuse as outsm
    float* outsm = (float*)patch;           // 2*16*OSS = 576 floats
    {
        float* outp = outsm + s * (KN * OSS);
        #pragma unroll
        for (int j = 0; j < 4; j++)
            outp[(kq + 4 * j) * OSS + b * 2 + px] = res[j];
    }
    __syncthreads();

    {
        int kk = t & 15, bb = t >> 4;       // row (bb,kk)
        float2 u = *(const float2*)&outsm[kk * OSS + bb * 2];
        float2 v = *(const float2*)&outsm[KN * OSS + kk * OSS + bb * 2];
        float2 r = make_float2(u.x + v.x, u.y + v.y);
        __stcs((float2*)&out[(((size_t)bb * KN + kk) << 14) + p0], r);
    }
}

extern "C" void kernel_launch(void* const* d_in, const int* in_sizes, int n_in,
                              void* d_out, int out_size) {
    const float*    x   = (const float*)d_in[0];
    const float*    w   = (const float*)d_in[1];
    const unsigned* hid = (const unsigned*)d_in[2];
    float*          out = (float*)d_out;
    (void)in_sizes; (void)n_in; (void)out_size;

    cudaFuncSetAttribute(abc2d_kernel,
                         cudaFuncAttributeMaxDynamicSharedMemorySize, SMEM_BYTES);
    transpose_kernel<<<IMG / 256, 256>>>(x, hid);
    abc2d_kernel<<<PP / NPX, NT, SMEM_BYTES>>>(w, hid, out);
}

// round 11
// speedup vs baseline: 1.5192x; 1.0885x over previous
#include <cuda_runtime.h>
#include <cuda_fp16.h>

#define BB    8
#define PP    16384
#define KN    16
#define CK    144
#define IMG   (16*128*128)    // 262144 = 2^18
#define NT    128
#define NPX   2
#define WKSTR  148                        // w k-row stride (floats); deg-2 banks
#define WPXSTR (KN*WKSTR + 4)             // 2372 floats; 16B-aligned, +4 bank offset
#define PPXB   (CK*16 + 16)               // 2320 B patch px stride (16B rows)

#define WFL        (NPX*WPXSTR)           // 4744 floats
#define SMEM_BYTES (WFL*4 + NPX*PPXB + 8) // 23624

// 4 MB scratch: x transposed + fp16-packed, batch-innermost (row = 16B)
__device__ __align__(16) __half g_xth[IMG * BB];
__device__ int g_idx_is64;

__device__ __forceinline__ void fma2(unsigned long long& d,
                                     unsigned long long a, unsigned long long b) {
    asm("fma.rn.f32x2 %0, %1, %2, %0;" : "+l"(d) : "l"(a), "l"(b));
}

// Transpose+pack x [B][IMG] -> g_xth [IMG][B]; block 0 probes idx dtype.
__global__ __launch_bounds__(256) void transpose_kernel(
    const float* __restrict__ x, const unsigned* __restrict__ h32)
{
    if (blockIdx.x == 0 && threadIdx.x < 32) {
        unsigned v = h32[2u * (threadIdx.x * 36000u) + 1u];
        int all0 = __all_sync(0xFFFFFFFFu, v == 0u);
        if (threadIdx.x == 0) g_idx_is64 = all0;
    }
    int i = blockIdx.x * 256 + threadIdx.x;
    __half2 h[4];
    #pragma unroll
    for (int q = 0; q < 4; q++) {
        float lo = __ldg(&x[(2 * q) * IMG + i]);
        float hi = __ldg(&x[(2 * q + 1) * IMG + i]);
        h[q] = __floats2half2_rn(lo, hi);
    }
    *(uint4*)&g_xth[(size_t)i * BB] = *(uint4*)h;
}

__global__ __launch_bounds__(NT, 9) void abc2d_kernel(
    const float* __restrict__ weights,
    const unsigned* __restrict__ hidx32,
    float* __restrict__ out)
{
    extern __shared__ __align__(16) float smem[];
    float*  wsm   = smem;                               // [px][16][WKSTR]
    __half* patch = (__half*)((char*)smem + WFL * 4);   // [px][c][8]
    unsigned mbar = (unsigned)__cvta_generic_to_shared((char*)smem + WFL * 4 + NPX * PPXB);

    const int p0 = blockIdx.x * NPX;
    const int t  = threadIdx.x;
    const int is64 = g_idx_is64;

    if (t == 0) {
        asm volatile("mbarrier.init.shared.b64 [%0], 1;" :: "r"(mbar) : "memory");
        asm volatile("mbarrier.arrive.expect_tx.shared.b64 _, [%0], %1;"
                     :: "r"(mbar), "r"(NPX * KN * CK * 4) : "memory");
    }
    __syncthreads();

    // ---- weights: 32 per-k-row bulk copies (576 B) into padded rows ----
    if (t < 32) {
        int px = t >> 4, k = t & 15;
        unsigned d = (unsigned)__cvta_generic_to_shared(wsm + px * WPXSTR + k * WKSTR);
        const float* src = weights + (size_t)(p0 + px) * (KN * CK) + k * CK;
        asm volatile(
            "{\n\t"
            ".reg .b64 pol;\n\t"
            "createpolicy.fractional.L2::evict_first.b64 pol, 1.0;\n\t"
            "cp.async.bulk.shared::cluster.global.mbarrier::complete_tx::bytes.L2::cache_hint"
            " [%0], [%1], %2, [%3], pol;\n\t"
            "}\n"
            :: "r"(d), "l"(src), "r"(CK * 4), "r"(mbar) : "memory");
    }

    // ---- gather (overlaps copies): 288 (px,c) tasks, LDG.128 -> STS.128 ----
    {
        #pragma unroll
        for (int r = 0; r < 3; r++) {
            int e = t + r * NT;
            if (r < 2 || t < 32) {                      // 128+128+32
                int px = e / CK;
                int c  = e - px * CK;
                int elem = (p0 + px) * CK + c;
                unsigned w = is64 ? __ldcs(&hidx32[2 * elem]) : __ldcs(&hidx32[elem]);
                uint4 v = __ldg((const uint4*)&g_xth[(size_t)(w & (IMG - 1)) * BB]);
                *(uint4*)((char*)patch + px * PPXB + c * 16) = v;
            }
        }
    }

    __syncthreads();          // patch visible

    // wait for weight copies
    asm volatile(
        "{\n\t"
        ".reg .pred P1;\n\t"
        "WL_%=:\n\t"
        "mbarrier.try_wait.parity.acquire.cta.shared::cta.b64 P1, [%0], 0, 0x989680;\n\t"
        "@P1 bra.uni WD_%=;\n\t"
        "bra.uni WL_%=;\n\t"
        "WD_%=:\n\t"
        "}\n"
        :: "r"(mbar) : "memory");

    // ---- compute: thread = (kp, px, s); 2 k-rows x 8 b over 18 c ----
    const int kp  = t & 7;
    const int cpx = (t >> 3) & 1;
    const int s   = t >> 4;
    float rr[2][8];
    {
        const float*  wr = wsm + cpx * WPXSTR + (kp * 2) * WKSTR;
        const __half* pr = (const __half*)((const char*)patch + cpx * PPXB);
        unsigned long long acc[2][4] = {{0ull,0ull,0ull,0ull},{0ull,0ull,0ull,0ull}};
        const int cb = s * 18;
        #pragma unroll
        for (int j = 0; j < 18; j++) {
            const int c = cb + j;
            uint4 praw = *(const uint4*)(pr + c * 8);    // 8 halves, broadcast row
            const __half2* ph = (const __half2*)&praw;
            float2 f0 = __half22float2(ph[0]);
            float2 f1 = __half22float2(ph[1]);
            float2 f2 = __half22float2(ph[2]);
            float2 f3 = __half22float2(ph[3]);
            unsigned long long pf0 = *(unsigned long long*)&f0;
            unsigned long long pf1 = *(unsigned long long*)&f1;
            unsigned long long pf2 = *(unsigned long long*)&f2;
            unsigned long long pf3 = *(unsigned long long*)&f3;
            float w0 = wr[c];
            float w1 = wr[WKSTR + c];
            unsigned long long W0, W1;
            asm("mov.b64 %0, {%1, %1};" : "=l"(W0) : "f"(w0));
            asm("mov.b64 %0, {%1, %1};" : "=l"(W1) : "f"(w1));
            fma2(acc[0][0], W0, pf0); fma2(acc[0][1], W0, pf1);
            fma2(acc[0][2], W0, pf2); fma2(acc[0][3], W0, pf3);
            fma2(acc[1][0], W1, pf0); fma2(acc[1][1], W1, pf1);
            fma2(acc[1][2], W1, pf2); fma2(acc[1][3], W1, pf3);
        }
        #pragma unroll
        for (int k1 = 0; k1 < 2; k1++)
            #pragma unroll
            for (int q = 0; q < 4; q++) {
                rr[k1][2 * q]     = __uint_as_float((unsigned)acc[k1][q]);
                rr[k1][2 * q + 1] = __uint_as_float((unsigned)(acc[k1][q] >> 32));
            }
    }
    // in-warp reduce over s-bit0 (lane bit 4)
    #pragma unroll
    for (int k1 = 0; k1 < 2; k1++)
        #pragma unroll
        for (int b = 0; b < 8; b++)
            rr[k1][b] += __shfl_xor_sync(0xFFFFFFFFu, rr[k1][b], 16);

    // ---- stage warp-partials (overlay patch), then final 4-way sum + STG ----
    __syncthreads();                        // patch reads done
    float* outsm = (float*)patch;           // [4 warps][2 px][8 b][16 k]
    if ((t & 16) == 0) {
        const int wg = t >> 5;
        float* dst = outsm + ((wg * 2 + cpx) * 8) * KN + kp * 2;
        #pragma unroll
        for (int b = 0; b < 8; b++)
            *(float2*)&dst[b * KN] = make_float2(rr[0][b], rr[1][b]);
    }
    __syncthreads();

    {
        const int k = t & 15, b = t >> 4;
        float s0 = 0.f, s1 = 0.f;
        #pragma unroll
        for (int wg = 0; wg < 4; wg++) {
            s0 += outsm[((wg * 2 + 0) * 8 + b) * KN + k];
            s1 += outsm[((wg * 2 + 1) * 8 + b) * KN + k];
        }
        __stcs((float2*)&out[(((size_t)b * KN + k) << 14) + p0], make_float2(s0, s1));
    }
}

extern "C" void kernel_launch(void* const* d_in, const int* in_sizes, int n_in,
                              void* d_out, int out_size) {
    const float*    x   = (const float*)d_in[0];
    const float*    w   = (const float*)d_in[1];
    const unsigned* hid = (const unsigned*)d_in[2];
    float*          out = (float*)d_out;
    (void)in_sizes; (void)n_in; (void)out_size;

    cudaFuncSetAttribute(abc2d_kernel,
                         cudaFuncAttributeMaxDynamicSharedMemorySize, SMEM_BYTES);
    transpose_kernel<<<IMG / 256, 256>>>(x, hid);
    abc2d_kernel<<<PP / NPX, NT, SMEM_BYTES>>>(w, hid, out);
}

// round 12
// speedup vs baseline: 1.5582x; 1.0256x over previous
#include <cuda_runtime.h>
#include <cuda_fp16.h>

#define BB    8
#define PP    16384
#define KN    16
#define CK    144
#define IMG   (16*128*128)    // 262144 = 2^18
#define NT    128
#define NPX   2
#define WKSTR  148                        // k-row stride (floats); 20*kp mod 32 = deg-1 perm
#define WPXSTR (KN*WKSTR)                 // 2368 floats; == 0 mod 32 (cpx via c-window shift)
#define PPXB   (CK*16)                    // 2304 B patch px stride (16B rows)

#define WFL        (NPX*WPXSTR)           // 4736 floats
#define SMEM_BYTES (WFL*4 + NPX*PPXB + 8) // 23560

// 4 MB scratch: x transposed + fp16-packed, batch-innermost (row = 16B)
__device__ __align__(16) __half g_xth[IMG * BB];
__device__ int g_idx_is64;

__device__ __forceinline__ void fma2(unsigned long long& d,
                                     unsigned long long a, unsigned long long b) {
    asm("fma.rn.f32x2 %0, %1, %2, %0;" : "+l"(d) : "l"(a), "l"(b));
}

// Transpose+pack x [B][IMG] -> g_xth [IMG][B]; block 0 probes idx dtype.
__global__ __launch_bounds__(256) void transpose_kernel(
    const float* __restrict__ x, const unsigned* __restrict__ h32)
{
    if (blockIdx.x == 0 && threadIdx.x < 32) {
        unsigned v = h32[2u * (threadIdx.x * 36000u) + 1u];
        int all0 = __all_sync(0xFFFFFFFFu, v == 0u);
        if (threadIdx.x == 0) g_idx_is64 = all0;
    }
    int i = blockIdx.x * 256 + threadIdx.x;
    __half2 h[4];
    #pragma unroll
    for (int q = 0; q < 4; q++) {
        float lo = __ldg(&x[(2 * q) * IMG + i]);
        float hi = __ldg(&x[(2 * q + 1) * IMG + i]);
        h[q] = __floats2half2_rn(lo, hi);
    }
    *(uint4*)&g_xth[(size_t)i * BB] = *(uint4*)h;
}

__global__ __launch_bounds__(NT, 9) void abc2d_kernel(
    const float* __restrict__ weights,
    const unsigned* __restrict__ hidx32,
    float* __restrict__ out)
{
    extern __shared__ __align__(16) float smem[];
    float*  wsm   = smem;                               // [px][16][WKSTR]
    __half* patch = (__half*)((char*)smem + WFL * 4);   // [px][c][8]
    unsigned mbar = (unsigned)__cvta_generic_to_shared((char*)smem + WFL * 4 + NPX * PPXB);

    const int p0 = blockIdx.x * NPX;
    const int t  = threadIdx.x;
    const int is64 = g_idx_is64;

    if (t == 0) {
        asm volatile("mbarrier.init.shared.b64 [%0], 1;" :: "r"(mbar) : "memory");
        asm volatile("mbarrier.arrive.expect_tx.shared.b64 _, [%0], %1;"
                     :: "r"(mbar), "r"(NPX * KN * CK * 4) : "memory");
    }
    __syncthreads();

    // ---- weights: 32 per-k-row bulk copies (576 B) into padded rows ----
    if (t < 32) {
        int px = t >> 4, k = t & 15;
        unsigned d = (unsigned)__cvta_generic_to_shared(wsm + px * WPXSTR + k * WKSTR);
        const float* src = weights + (size_t)(p0 + px) * (KN * CK) + k * CK;
        asm volatile(
            "{\n\t"
            ".reg .b64 pol;\n\t"
            "createpolicy.fractional.L2::evict_first.b64 pol, 1.0;\n\t"
            "cp.async.bulk.shared::cluster.global.mbarrier::complete_tx::bytes.L2::cache_hint"
            " [%0], [%1], %2, [%3], pol;\n\t"
            "}\n"
            :: "r"(d), "l"(src), "r"(CK * 4), "r"(mbar) : "memory");
    }

    // ---- gather (overlaps copies): 144 pair-tasks; paired idx, 2 LDG.128 each ----
    {
        #pragma unroll
        for (int r = 0; r < 2; r++) {
            int e = t + r * NT;
            if (r == 0 || t < (NPX * CK / 2 - NT)) {    // 128 + 16
                int px = e / (CK / 2);
                int c0 = (e - px * (CK / 2)) * 2;
                int elem = (p0 + px) * CK + c0;         // even -> aligned vec loads
                unsigned i0, i1;
                if (is64) {
                    uint4 v = __ldcs((const uint4*)&hidx32[2 * elem]);
                    i0 = v.x; i1 = v.z;
                } else {
                    uint2 v = __ldcs((const uint2*)&hidx32[elem]);
                    i0 = v.x; i1 = v.y;
                }
                uint4 v0 = __ldg((const uint4*)&g_xth[(size_t)(i0 & (IMG - 1)) * BB]);
                uint4 v1 = __ldg((const uint4*)&g_xth[(size_t)(i1 & (IMG - 1)) * BB]);
                char* pb = (char*)patch + px * PPXB;
                *(uint4*)(pb + c0 * 16)      = v0;
                *(uint4*)(pb + c0 * 16 + 16) = v1;
            }
        }
    }

    __syncthreads();          // patch visible

    // wait for weight copies
    asm volatile(
        "{\n\t"
        ".reg .pred P1;\n\t"
        "WL_%=:\n\t"
        "mbarrier.try_wait.parity.acquire.cta.shared::cta.b64 P1, [%0], 0, 0x989680;\n\t"
        "@P1 bra.uni WD_%=;\n\t"
        "bra.uni WL_%=;\n\t"
        "WD_%=:\n\t"
        "}\n"
        :: "r"(mbar) : "memory");

    // ---- compute: thread = (kp, cpx, s); k-rows (kp, kp+8), c-window 18s+9*cpx ----
    const int kp  = t & 7;
    const int cpx = (t >> 3) & 1;
    const int s   = t >> 4;
    const int cb  = s * 18 + cpx * 9;
    float rr0[8], rr1[8];
    {
        const float* wr = wsm + cpx * WPXSTR + kp * WKSTR;
        const char*  pb = (const char*)patch + cpx * PPXB;
        unsigned long long a0[4] = {0ull,0ull,0ull,0ull};
        unsigned long long a1[4] = {0ull,0ull,0ull,0ull};
        #pragma unroll
        for (int j = 0; j < 18; j++) {
            int c = cb + j;
            if (c >= CK) c -= CK;
            uint4 praw = *(const uint4*)(pb + c * 16);   // 8 halves, broadcast row
            const __half2* ph = (const __half2*)&praw;
            float2 f0 = __half22float2(ph[0]);
            float2 f1 = __half22float2(ph[1]);
            float2 f2 = __half22float2(ph[2]);
            float2 f3 = __half22float2(ph[3]);
            unsigned long long pf0 = *(unsigned long long*)&f0;
            unsigned long long pf1 = *(unsigned long long*)&f1;
            unsigned long long pf2 = *(unsigned long long*)&f2;
            unsigned long long pf3 = *(unsigned long long*)&f3;
            float w0 = wr[c];
            float w1 = wr[8 * WKSTR + c];
            unsigned long long W0, W1;
            asm("mov.b64 %0, {%1, %1};" : "=l"(W0) : "f"(w0));
            asm("mov.b64 %0, {%1, %1};" : "=l"(W1) : "f"(w1));
            fma2(a0[0], W0, pf0); fma2(a0[1], W0, pf1);
            fma2(a0[2], W0, pf2); fma2(a0[3], W0, pf3);
            fma2(a1[0], W1, pf0); fma2(a1[1], W1, pf1);
            fma2(a1[2], W1, pf2); fma2(a1[3], W1, pf3);
        }
        #pragma unroll
        for (int q = 0; q < 4; q++) {
            rr0[2 * q]     = __uint_as_float((unsigned)a0[q]);
            rr0[2 * q + 1] = __uint_as_float((unsigned)(a0[q] >> 32));
            rr1[2 * q]     = __uint_as_float((unsigned)a1[q]);
            rr1[2 * q + 1] = __uint_as_float((unsigned)(a1[q] >> 32));
        }
    }
    // in-warp reduce over s-low bit (lane bit 4)
    #pragma unroll
    for (int b = 0; b < 8; b++) {
        rr0[b] += __shfl_xor_sync(0xFFFFFFFFu, rr0[b], 16);
        rr1[b] += __shfl_xor_sync(0xFFFFFFFFu, rr1[b], 16);
    }

    // ---- stage warp-partials (overlay patch): [wg][cpx][b][kp*2+half] ----
    __syncthreads();                        // patch reads done
    float* outsm = (float*)patch;           // 4*2*8*16 = 1024 floats
    if ((t & 16) == 0) {
        const int wg = t >> 5;
        float* dst = outsm + ((wg * 2 + cpx) * 8) * KN + kp * 2;
        #pragma unroll
        for (int b = 0; b < 8; b++)
            *(float2*)&dst[b * KN] = make_float2(rr0[b], rr1[b]);
    }
    __syncthreads();

    {
        const int k = t & 15, b = t >> 4;
        const int ki = (k & 7) * 2 + (k >> 3);      // slot for k in (kp, kp+8) pairing
        float s0 = 0.f, s1 = 0.f;
        #pragma unroll
        for (int wg = 0; wg < 4; wg++) {
            s0 += outsm[((wg * 2 + 0) * 8 + b) * KN + ki];
            s1 += outsm[((wg * 2 + 1) * 8 + b) * KN + ki];
        }
        __stcs((float2*)&out[(((size_t)b * KN + k) << 14) + p0], make_float2(s0, s1));
    }
}

extern "C" void kernel_launch(void* const* d_in, const int* in_sizes, int n_in,
                              void* d_out, int out_size) {
    const float*    x   = (const float*)d_in[0];
    const float*    w   = (const float*)d_in[1];
    const unsigned* hid = (const unsigned*)d_in[2];
    float*          out = (float*)d_out;
    (void)in_sizes; (void)n_in; (void)out_size;

    cudaFuncSetAttribute(abc2d_kernel,
                         cudaFuncAttributeMaxDynamicSharedMemorySize, SMEM_BYTES);
    transpose_kernel<<<IMG / 256, 256>>>(x, hid);
    abc2d_kernel<<<PP / NPX, NT, SMEM_BYTES>>>(w, hid, out);
}